// round 1
// baseline (speedup 1.0000x reference)
#include <cuda_runtime.h>
#include <cuda_bf16.h>
#include <math.h>

// Problem shape (fixed by setup_inputs): inputs [4096,512] fp32, targets [4096] int32.
#define N 4096
#define D 512
#define MARGIN 1.0f

#define BM 128
#define BN 128
#define BK 16
#define NTHREADS 256
#define KTILES (D / BK) // 32

// ---------------- scratch (no allocations allowed) ----------------
__device__ float g_mag[N];
__device__ float g_rowneg[N];
__device__ double g_loss;
__device__ unsigned long long g_cnt;

// ---------------- init ----------------
__global__ void k_init() {
    int t = blockIdx.x * blockDim.x + threadIdx.x;
    if (t < N) g_rowneg[t] = 0.0f;
    if (t == 0) { g_loss = 0.0; g_cnt = 0ULL; }
}

// ---------------- mag[i] = sum_k x[i][k]^2 ----------------
__global__ void k_mag(const float* __restrict__ X) {
    int i = blockIdx.x;
    int tid = threadIdx.x;                       // 128 threads
    const float4* x4 = (const float4*)(X + (size_t)i * D);
    float4 v = x4[tid];                          // D/4 == 128
    float s = v.x * v.x + v.y * v.y + v.z * v.z + v.w * v.w;
    // warp reduce
    for (int o = 16; o > 0; o >>= 1) s += __shfl_down_sync(0xffffffffu, s, o);
    __shared__ float ws[4];
    if ((tid & 31) == 0) ws[tid >> 5] = s;
    __syncthreads();
    if (tid == 0) g_mag[i] = ws[0] + ws[1] + ws[2] + ws[3];
}

// ---------------- main pass: symmetric GEMM + row_neg epilogue ----------------
// Computes C = X X^T only for block tiles with bi <= bj. For each element:
//   d2 = relu(mag_i + mag_j - 2*sim), dist = sqrt(d2)
//   e  = (label_i != label_j && dist > 0) ? exp(MARGIN - dist) : 0
// Off-diagonal tiles scatter e into row_neg[i] (row sums) AND row_neg[j]
// (col sums, by symmetry). Diagonal tiles scatter rows only.
__global__ void __launch_bounds__(NTHREADS, 2)
k_rowneg(const float* __restrict__ X, const int* __restrict__ lab) {
    const int bj = blockIdx.x;
    const int bi = blockIdx.y;
    if (bi > bj) return;

    __shared__ float As[BK][BM];
    __shared__ float Bs[BK][BN];
    __shared__ float sRow[BM];
    __shared__ float sCol[BN];

    const int tid = threadIdx.x;
    const int tx = tid & 15;      // 0..15
    const int ty = tid >> 4;      // 0..15

    const int lr  = tid >> 2;     // load row within tile half (0..63)
    const int c4  = (tid & 3) * 4;

    const float* Abase = X + (size_t)(bi * BM + lr) * D + c4;
    const float* Bbase = X + (size_t)(bj * BN + lr) * D + c4;

    float acc[8][8];
#pragma unroll
    for (int m = 0; m < 8; m++)
#pragma unroll
        for (int n = 0; n < 8; n++) acc[m][n] = 0.0f;

    float4 pa0, pa1, pb0, pb1;

    // prologue load kt=0
    pa0 = *(const float4*)(Abase);
    pa1 = *(const float4*)(Abase + (size_t)64 * D);
    pb0 = *(const float4*)(Bbase);
    pb1 = *(const float4*)(Bbase + (size_t)64 * D);

#pragma unroll 1
    for (int kt = 0; kt < KTILES; kt++) {
        // store staged tile to smem
        As[c4 + 0][lr] = pa0.x; As[c4 + 1][lr] = pa0.y; As[c4 + 2][lr] = pa0.z; As[c4 + 3][lr] = pa0.w;
        As[c4 + 0][lr + 64] = pa1.x; As[c4 + 1][lr + 64] = pa1.y; As[c4 + 2][lr + 64] = pa1.z; As[c4 + 3][lr + 64] = pa1.w;
        Bs[c4 + 0][lr] = pb0.x; Bs[c4 + 1][lr] = pb0.y; Bs[c4 + 2][lr] = pb0.z; Bs[c4 + 3][lr] = pb0.w;
        Bs[c4 + 0][lr + 64] = pb1.x; Bs[c4 + 1][lr + 64] = pb1.y; Bs[c4 + 2][lr + 64] = pb1.z; Bs[c4 + 3][lr + 64] = pb1.w;
        __syncthreads();

        // prefetch next k-tile from global while computing
        if (kt + 1 < KTILES) {
            const float* An = Abase + (kt + 1) * BK;
            const float* Bn = Bbase + (kt + 1) * BK;
            pa0 = *(const float4*)(An);
            pa1 = *(const float4*)(An + (size_t)64 * D);
            pb0 = *(const float4*)(Bn);
            pb1 = *(const float4*)(Bn + (size_t)64 * D);
        }

#pragma unroll
        for (int k = 0; k < BK; k++) {
            float4 a0 = *(const float4*)&As[k][ty * 8];
            float4 a1 = *(const float4*)&As[k][ty * 8 + 4];
            float4 b0 = *(const float4*)&Bs[k][tx * 8];
            float4 b1 = *(const float4*)&Bs[k][tx * 8 + 4];
            float a[8] = {a0.x, a0.y, a0.z, a0.w, a1.x, a1.y, a1.z, a1.w};
            float b[8] = {b0.x, b0.y, b0.z, b0.w, b1.x, b1.y, b1.z, b1.w};
#pragma unroll
            for (int m = 0; m < 8; m++)
#pragma unroll
                for (int n = 0; n < 8; n++) acc[m][n] = fmaf(a[m], b[n], acc[m][n]);
        }
        __syncthreads();
    }

    // -------- epilogue --------
    const int ibase = bi * BM + ty * 8;
    const int jbase = bj * BN + tx * 8;
    const bool diag = (bi == bj);

    float magI[8], magJ[8];
    int li[8], lj[8];
#pragma unroll
    for (int m = 0; m < 8; m++) { magI[m] = g_mag[ibase + m]; li[m] = lab[ibase + m]; }
#pragma unroll
    for (int n = 0; n < 8; n++) { magJ[n] = g_mag[jbase + n]; lj[n] = lab[jbase + n]; }

    float rs[8] = {0, 0, 0, 0, 0, 0, 0, 0};
    float cs[8] = {0, 0, 0, 0, 0, 0, 0, 0};
#pragma unroll
    for (int m = 0; m < 8; m++) {
#pragma unroll
        for (int n = 0; n < 8; n++) {
            float d2 = fmaxf(magI[m] + magJ[n] - 2.0f * acc[m][n], 0.0f);
            float dist = sqrtf(d2);
            float e = 0.0f;
            if ((li[m] != lj[n]) && (dist > 0.0f)) e = __expf(MARGIN - dist);
            rs[m] += e;
            cs[n] += e;
        }
    }

    if (tid < BM) { sRow[tid] = 0.0f; sCol[tid] = 0.0f; }
    __syncthreads();
#pragma unroll
    for (int m = 0; m < 8; m++) atomicAdd(&sRow[ty * 8 + m], rs[m]);
    if (!diag) {
#pragma unroll
        for (int n = 0; n < 8; n++) atomicAdd(&sCol[tx * 8 + n], cs[n]);
    }
    __syncthreads();
    if (tid < BM) {
        atomicAdd(&g_rowneg[bi * BM + tid], sRow[tid]);
        if (!diag) atomicAdd(&g_rowneg[bj * BN + tid], sCol[tid]);
    }
}

// ---------------- positive-pair loss ----------------
// One block per row i; threads scan j > i with matching label (~31 per row),
// recompute the dot product directly (X is L2-resident).
__global__ void k_loss(const float* __restrict__ X, const int* __restrict__ lab) {
    const int i = blockIdx.x;
    const int tid = threadIdx.x; // 128

    __shared__ float4 xi[D / 4];
    const float4* xrow = (const float4*)(X + (size_t)i * D);
    xi[tid] = xrow[tid];         // 128 threads * float4 = 512 floats
    __syncthreads();

    const int myl = lab[i];
    const float mi = g_mag[i];
    const float rni = g_rowneg[i];

    double lsum = 0.0;
    unsigned c = 0;
    for (int j = i + 1 + tid; j < N; j += blockDim.x) {
        if (lab[j] != myl) continue;
        const float4* xj = (const float4*)(X + (size_t)j * D);
        float dot = 0.0f;
#pragma unroll 8
        for (int k = 0; k < D / 4; k++) {
            float4 a = xi[k];
            float4 b = xj[k];
            dot += a.x * b.x + a.y * b.y + a.z * b.z + a.w * b.w;
        }
        float d2 = fmaxf(mi + g_mag[j] - 2.0f * dot, 0.0f);
        float dist = sqrtf(d2);
        float J = logf(rni + g_rowneg[j]) + dist;
        float l = fmaxf(J, 0.0f);
        lsum += (double)l * (double)l;
        c++;
    }

    __shared__ double sl[128];
    __shared__ unsigned sc[128];
    sl[tid] = lsum;
    sc[tid] = c;
    __syncthreads();
    for (int s = 64; s > 0; s >>= 1) {
        if (tid < s) { sl[tid] += sl[tid + s]; sc[tid] += sc[tid + s]; }
        __syncthreads();
    }
    if (tid == 0 && sc[0] > 0) {
        atomicAdd(&g_loss, sl[0]);
        atomicAdd(&g_cnt, (unsigned long long)sc[0]);
    }
}

// ---------------- finalize ----------------
__global__ void k_final(float* __restrict__ out) {
    // len_p counts SYMMETRIC positive pairs = 2 * upper-triangle count
    out[0] = (float)(g_loss / (double)(2ULL * g_cnt));
}

extern "C" void kernel_launch(void* const* d_in, const int* in_sizes, int n_in,
                              void* d_out, int out_size) {
    const float* X = (const float*)d_in[0];
    const int* lab = (const int*)d_in[1];
    float* out = (float*)d_out;

    k_init<<<(N + 255) / 256, 256>>>();
    k_mag<<<N, 128>>>(X);
    dim3 grid(N / BN, N / BM);
    k_rowneg<<<grid, NTHREADS>>>(X, lab);
    k_loss<<<N, 128>>>(X, lab);
    k_final<<<1, 1>>>(out);
}

// round 2
// speedup vs baseline: 1.8387x; 1.8387x over previous
#include <cuda_runtime.h>
#include <cuda_bf16.h>
#include <math.h>

// Problem shape (fixed by setup_inputs): inputs [4096,512] fp32, targets [4096] int32.
#define N 4096
#define D 512
#define MARGIN 1.0f

#define BM 128
#define BN 128
#define BK 16
#define NTHREADS 256
#define KTILES (D / BK) // 32

#define MAXPOS (N * (N - 1) / 2) // worst case all-same-label: 8386560

// ---------------- scratch (no allocations allowed) ----------------
__device__ float g_mag[N];
__device__ float g_rowneg[N];
__device__ double g_loss;
__device__ unsigned int g_npos;
__device__ unsigned int g_pos_key[MAXPOS];   // (i << 12) | j, i < j
__device__ float g_pos_dist[MAXPOS];

// ---------------- init ----------------
__global__ void k_init() {
    int t = blockIdx.x * blockDim.x + threadIdx.x;
    if (t < N) g_rowneg[t] = 0.0f;
    if (t == 0) { g_loss = 0.0; g_npos = 0u; }
}

// ---------------- mag[i] = sum_k x[i][k]^2 ----------------
__global__ void k_mag(const float* __restrict__ X) {
    int i = blockIdx.x;
    int tid = threadIdx.x;                       // 128 threads
    const float4* x4 = (const float4*)(X + (size_t)i * D);
    float4 v = x4[tid];                          // D/4 == 128
    float s = v.x * v.x + v.y * v.y + v.z * v.z + v.w * v.w;
    for (int o = 16; o > 0; o >>= 1) s += __shfl_down_sync(0xffffffffu, s, o);
    __shared__ float ws[4];
    if ((tid & 31) == 0) ws[tid >> 5] = s;
    __syncthreads();
    if (tid == 0) g_mag[i] = ws[0] + ws[1] + ws[2] + ws[3];
}

// ---------------- main pass: symmetric GEMM + fused epilogue ----------------
// Computes C = X X^T only for block tiles with bi <= bj. For each element:
//   d2 = relu(mag_i + mag_j - 2*sim), dist = sqrt(d2)
//   negatives (label mismatch, dist>0): e = exp(MARGIN - dist) scattered into
//     row_neg[i] and (off-diag tiles) row_neg[j]
//   positives (label match, global i<j): append (i,j,dist) to the pair list
__global__ void __launch_bounds__(NTHREADS, 2)
k_rowneg(const float* __restrict__ X, const int* __restrict__ lab) {
    const int bj = blockIdx.x;
    const int bi = blockIdx.y;
    if (bi > bj) return;

    __shared__ float As[BK][BM];
    __shared__ float Bs[BK][BN];
    __shared__ float sRow[BM];
    __shared__ float sCol[BN];

    const int tid = threadIdx.x;
    const int tx = tid & 15;      // 0..15
    const int ty = tid >> 4;      // 0..15

    const int lr  = tid >> 2;     // load row within tile half (0..63)
    const int c4  = (tid & 3) * 4;

    const float* Abase = X + (size_t)(bi * BM + lr) * D + c4;
    const float* Bbase = X + (size_t)(bj * BN + lr) * D + c4;

    float acc[8][8];
#pragma unroll
    for (int m = 0; m < 8; m++)
#pragma unroll
        for (int n = 0; n < 8; n++) acc[m][n] = 0.0f;

    float4 pa0, pa1, pb0, pb1;

    // prologue load kt=0
    pa0 = *(const float4*)(Abase);
    pa1 = *(const float4*)(Abase + (size_t)64 * D);
    pb0 = *(const float4*)(Bbase);
    pb1 = *(const float4*)(Bbase + (size_t)64 * D);

#pragma unroll 1
    for (int kt = 0; kt < KTILES; kt++) {
        As[c4 + 0][lr] = pa0.x; As[c4 + 1][lr] = pa0.y; As[c4 + 2][lr] = pa0.z; As[c4 + 3][lr] = pa0.w;
        As[c4 + 0][lr + 64] = pa1.x; As[c4 + 1][lr + 64] = pa1.y; As[c4 + 2][lr + 64] = pa1.z; As[c4 + 3][lr + 64] = pa1.w;
        Bs[c4 + 0][lr] = pb0.x; Bs[c4 + 1][lr] = pb0.y; Bs[c4 + 2][lr] = pb0.z; Bs[c4 + 3][lr] = pb0.w;
        Bs[c4 + 0][lr + 64] = pb1.x; Bs[c4 + 1][lr + 64] = pb1.y; Bs[c4 + 2][lr + 64] = pb1.z; Bs[c4 + 3][lr + 64] = pb1.w;
        __syncthreads();

        if (kt + 1 < KTILES) {
            const float* An = Abase + (kt + 1) * BK;
            const float* Bn = Bbase + (kt + 1) * BK;
            pa0 = *(const float4*)(An);
            pa1 = *(const float4*)(An + (size_t)64 * D);
            pb0 = *(const float4*)(Bn);
            pb1 = *(const float4*)(Bn + (size_t)64 * D);
        }

#pragma unroll
        for (int k = 0; k < BK; k++) {
            float4 a0 = *(const float4*)&As[k][ty * 8];
            float4 a1 = *(const float4*)&As[k][ty * 8 + 4];
            float4 b0 = *(const float4*)&Bs[k][tx * 8];
            float4 b1 = *(const float4*)&Bs[k][tx * 8 + 4];
            float a[8] = {a0.x, a0.y, a0.z, a0.w, a1.x, a1.y, a1.z, a1.w};
            float b[8] = {b0.x, b0.y, b0.z, b0.w, b1.x, b1.y, b1.z, b1.w};
#pragma unroll
            for (int m = 0; m < 8; m++)
#pragma unroll
                for (int n = 0; n < 8; n++) acc[m][n] = fmaf(a[m], b[n], acc[m][n]);
        }
        __syncthreads();
    }

    // -------- epilogue --------
    const int ibase = bi * BM + ty * 8;
    const int jbase = bj * BN + tx * 8;
    const bool diag = (bi == bj);

    float magI[8], magJ[8];
    int li[8], lj[8];
#pragma unroll
    for (int m = 0; m < 8; m++) { magI[m] = g_mag[ibase + m]; li[m] = lab[ibase + m]; }
#pragma unroll
    for (int n = 0; n < 8; n++) { magJ[n] = g_mag[jbase + n]; lj[n] = lab[jbase + n]; }

    float rs[8] = {0, 0, 0, 0, 0, 0, 0, 0};
    float cs[8] = {0, 0, 0, 0, 0, 0, 0, 0};
#pragma unroll
    for (int m = 0; m < 8; m++) {
        const int gi = ibase + m;
#pragma unroll
        for (int n = 0; n < 8; n++) {
            const int gj = jbase + n;
            float d2 = fmaxf(magI[m] + magJ[n] - 2.0f * acc[m][n], 0.0f);
            float dist = sqrtf(d2);
            if (li[m] != lj[n]) {
                float e = (dist > 0.0f) ? __expf(MARGIN - dist) : 0.0f;
                rs[m] += e;
                cs[n] += e;
            } else if (gi < gj) {
                // positive upper-triangle pair: record for the loss pass
                unsigned idx = atomicAdd(&g_npos, 1u);
                g_pos_key[idx] = ((unsigned)gi << 12) | (unsigned)gj;
                g_pos_dist[idx] = dist;
            }
        }
    }

    if (tid < BM) { sRow[tid] = 0.0f; sCol[tid] = 0.0f; }
    __syncthreads();
#pragma unroll
    for (int m = 0; m < 8; m++) atomicAdd(&sRow[ty * 8 + m], rs[m]);
    if (!diag) {
#pragma unroll
        for (int n = 0; n < 8; n++) atomicAdd(&sCol[tx * 8 + n], cs[n]);
    }
    __syncthreads();
    if (tid < BM) {
        atomicAdd(&g_rowneg[bi * BM + tid], sRow[tid]);
        if (!diag) atomicAdd(&g_rowneg[bj * BN + tid], sCol[tid]);
    }
}

// ---------------- positive-pair loss over the recorded list ----------------
__global__ void k_loss2() {
    const unsigned total = g_npos;
    double lsum = 0.0;
    for (unsigned t = blockIdx.x * blockDim.x + threadIdx.x; t < total;
         t += gridDim.x * blockDim.x) {
        unsigned key = g_pos_key[t];
        float dist = g_pos_dist[t];
        int i = key >> 12;
        int j = key & 4095;
        float J = logf(g_rowneg[i] + g_rowneg[j]) + dist;
        float l = fmaxf(J, 0.0f);
        lsum += (double)l * (double)l;
    }
    // block reduce
    __shared__ double sl[256];
    int tid = threadIdx.x;
    sl[tid] = lsum;
    __syncthreads();
    for (int s = 128; s > 0; s >>= 1) {
        if (tid < s) sl[tid] += sl[tid + s];
        __syncthreads();
    }
    if (tid == 0 && sl[0] != 0.0) atomicAdd(&g_loss, sl[0]);
}

// ---------------- finalize ----------------
__global__ void k_final(float* __restrict__ out) {
    // len_p counts SYMMETRIC positive pairs = 2 * upper-triangle count
    out[0] = (float)(g_loss / (double)(2ULL * (unsigned long long)g_npos));
}

extern "C" void kernel_launch(void* const* d_in, const int* in_sizes, int n_in,
                              void* d_out, int out_size) {
    const float* X = (const float*)d_in[0];
    const int* lab = (const int*)d_in[1];
    float* out = (float*)d_out;

    k_init<<<(N + 255) / 256, 256>>>();
    k_mag<<<N, 128>>>(X);
    dim3 grid(N / BN, N / BM);
    k_rowneg<<<grid, NTHREADS>>>(X, lab);
    k_loss2<<<256, 256>>>();
    k_final<<<1, 1>>>(out);
}

// round 4
// speedup vs baseline: 6.4775x; 3.5228x over previous
#include <cuda_runtime.h>
#include <cuda_bf16.h>
#include <math.h>
#include <stdint.h>

// Problem shape (fixed): inputs [4096,512] fp32, targets [4096] int32.
#define N 4096
#define D 512
#define MARGIN 1.0f

#define TILE 128
#define NTILES (N / TILE)                         // 32
#define NPAIR_TILES (NTILES * (NTILES + 1) / 2)   // 528
#define KTOT 1024                                 // hi(512) + lo(512) bf16
#define KCH 64                                    // bf16 per K-stage (128 B/row)
#define NCHUNK (KTOT / KCH)                       // 16
#define GTHREADS 256
#define CAP 1024                                  // smem positive-pair buffer per CTA

#define MAXPOS (N * (N - 1) / 2)

// ---------------- device scratch (no allocations allowed) ----------------
__device__ float g_mag[N];
__device__ float g_rowneg[N];
__device__ double g_loss;
__device__ unsigned g_npos;
__device__ unsigned g_pos_key[MAXPOS];  // (i << 12) | j, i < j
__device__ float g_pos_dist[MAXPOS];
__device__ __nv_bfloat16 g_Xs[(size_t)N * KTOT];  // [row][0:512]=hi, [512:1024]=lo

// ---------------- PTX helpers (baseline PTX only: sm_80+ features) ----------------
__device__ __forceinline__ uint32_t smem_u32(const void* p) {
    uint32_t a;
    asm("{ .reg .u64 t; cvta.to.shared.u64 t, %1; cvt.u32.u64 %0, t; }"
        : "=r"(a) : "l"(p));
    return a;
}

#define CP_ASYNC16(dst, src) \
    asm volatile("cp.async.cg.shared.global [%0], [%1], 16;" \
                 :: "r"(dst), "l"(src) : "memory")
#define CP_COMMIT() asm volatile("cp.async.commit_group;" ::: "memory")
#define CP_WAIT(n)  asm volatile("cp.async.wait_group %0;" :: "n"(n) : "memory")

__device__ __forceinline__ void ldmatrix_x4(uint32_t& r0, uint32_t& r1,
                                            uint32_t& r2, uint32_t& r3,
                                            uint32_t addr) {
    asm volatile("ldmatrix.sync.aligned.m8n8.x4.shared.b16 {%0,%1,%2,%3}, [%4];"
                 : "=r"(r0), "=r"(r1), "=r"(r2), "=r"(r3) : "r"(addr));
}
__device__ __forceinline__ void ldmatrix_x2(uint32_t& r0, uint32_t& r1,
                                            uint32_t addr) {
    asm volatile("ldmatrix.sync.aligned.m8n8.x2.shared.b16 {%0,%1}, [%2];"
                 : "=r"(r0), "=r"(r1) : "r"(addr));
}
__device__ __forceinline__ void mma_bf16(float* d, const uint32_t* a,
                                         const uint32_t* b) {
    asm volatile(
        "mma.sync.aligned.m16n8k16.row.col.f32.bf16.bf16.f32 "
        "{%0,%1,%2,%3}, {%4,%5,%6,%7}, {%8,%9}, {%0,%1,%2,%3};"
        : "+f"(d[0]), "+f"(d[1]), "+f"(d[2]), "+f"(d[3])
        : "r"(a[0]), "r"(a[1]), "r"(a[2]), "r"(a[3]), "r"(b[0]), "r"(b[1]));
}

__device__ __forceinline__ uint32_t swz(uint32_t off) {
    return off ^ ((off >> 3) & 0x70);
}

// ---------------- init ----------------
__global__ void k_init() {
    int t = blockIdx.x * blockDim.x + threadIdx.x;
    if (t < N) g_rowneg[t] = 0.0f;
    if (t == 0) { g_loss = 0.0; g_npos = 0u; }
}

// ---------------- prep: mag + exact bf16 hi/lo split ----------------
__global__ void k_prep(const float* __restrict__ X) {
    const int i = blockIdx.x;
    const int tid = threadIdx.x;  // 128
    float4 v = ((const float4*)(X + (size_t)i * D))[tid];
    float s = v.x * v.x + v.y * v.y + v.z * v.z + v.w * v.w;
    for (int o = 16; o > 0; o >>= 1) s += __shfl_down_sync(0xffffffffu, s, o);
    __shared__ float ws[4];
    if ((tid & 31) == 0) ws[tid >> 5] = s;

    __nv_bfloat16 h0 = __float2bfloat16(v.x), h1 = __float2bfloat16(v.y);
    __nv_bfloat16 h2 = __float2bfloat16(v.z), h3 = __float2bfloat16(v.w);
    __nv_bfloat16 l0 = __float2bfloat16(v.x - __bfloat162float(h0));
    __nv_bfloat16 l1 = __float2bfloat16(v.y - __bfloat162float(h1));
    __nv_bfloat16 l2 = __float2bfloat16(v.z - __bfloat162float(h2));
    __nv_bfloat16 l3 = __float2bfloat16(v.w - __bfloat162float(h3));

    __nv_bfloat162* ph = (__nv_bfloat162*)(g_Xs + (size_t)i * KTOT + tid * 4);
    ph[0] = __halves2bfloat162(h0, h1);
    ph[1] = __halves2bfloat162(h2, h3);
    __nv_bfloat162* pl = (__nv_bfloat162*)(g_Xs + (size_t)i * KTOT + 512 + tid * 4);
    pl[0] = __halves2bfloat162(l0, l1);
    pl[1] = __halves2bfloat162(l2, l3);

    __syncthreads();
    if (tid == 0) g_mag[i] = ws[0] + ws[1] + ws[2] + ws[3];
}

// ---------------- main pass: HMMA symmetric GEMM + fused epilogue ----------------
// 8 warps, each owns a 64x32 sub-tile (warp grid 2x4) via m16n8k16 bf16 MMA.
__global__ void __launch_bounds__(GTHREADS, 2)
k_gemm(const int* __restrict__ lab) {
    __shared__ float sMagI[TILE], sMagJ[TILE];
    __shared__ int sLabI[TILE], sLabJ[TILE];
    __shared__ float sRow[TILE], sCol[TILE];
    __shared__ unsigned sPosKey[CAP];
    __shared__ float sPosDist[CAP];
    __shared__ unsigned sNpos, sBase;
    extern __shared__ char dsm[];

    const int tid = threadIdx.x;
    const int wid = tid >> 5;
    const int lid = tid & 31;
    const int wm = wid >> 2;      // warp row 0..1 -> m offset 0/64
    const int wn = wid & 3;       // warp col 0..3 -> n offset 0/32/64/96
    const int m0w = wm * 64;
    const int n0w = wn * 32;

    // decode upper-triangle tile (bi <= bj)
    int t = blockIdx.x, bi = 0;
    while (t >= NTILES - bi) { t -= NTILES - bi; bi++; }
    const int bj = bi + t;
    const bool diag = (bi == bj);
    const int gi0 = bi * TILE, gj0 = bj * TILE;

    // dynamic smem: [A0(16K) B0(16K) A1(16K) B1(16K)], 1024-aligned
    const uint32_t tbase = (smem_u32(dsm) + 1023u) & ~1023u;

    if (tid == 0) sNpos = 0u;
    if (tid < TILE) {
        sMagI[tid] = g_mag[gi0 + tid];
        sLabI[tid] = lab[gi0 + tid];
        sMagJ[tid] = g_mag[gj0 + tid];
        sLabJ[tid] = lab[gj0 + tid];
        sRow[tid] = 0.0f;
        sCol[tid] = 0.0f;
    }

    float acc[4][4][4];
#pragma unroll
    for (int mt = 0; mt < 4; mt++)
#pragma unroll
        for (int nt = 0; nt < 4; nt++)
#pragma unroll
            for (int r = 0; r < 4; r++) acc[mt][nt][r] = 0.0f;

    const __nv_bfloat16* gA = g_Xs + (size_t)gi0 * KTOT;
    const __nv_bfloat16* gB = g_Xs + (size_t)gj0 * KTOT;

    // per-thread load coords (4 x 16B chunks per tile per stage)
    const int lrow[4] = {(tid + 0) >> 3, (tid + 256) >> 3, (tid + 512) >> 3, (tid + 768) >> 3};
    const int lkc = tid & 7;

    // ---- issue stage 0 ----
    {
        const uint32_t bufA = tbase, bufB = tbase + 16384u;
#pragma unroll
        for (int i = 0; i < 4; i++) {
            uint32_t off = swz(lrow[i] * 128 + lkc * 16);
            CP_ASYNC16(bufA + off, (const char*)(gA + (size_t)lrow[i] * KTOT) + lkc * 16);
        }
        if (!diag) {
#pragma unroll
            for (int i = 0; i < 4; i++) {
                uint32_t off = swz(lrow[i] * 128 + lkc * 16);
                CP_ASYNC16(bufB + off, (const char*)(gB + (size_t)lrow[i] * KTOT) + lkc * 16);
            }
        }
        CP_COMMIT();
    }

#pragma unroll 1
    for (int c = 0; c < NCHUNK; c++) {
        if (c + 1 < NCHUNK) {
            const uint32_t bufA = tbase + ((c + 1) & 1) * 32768u;
            const uint32_t bufB = bufA + 16384u;
            const char* srcA = (const char*)(gA + (c + 1) * KCH);
            const char* srcB = (const char*)(gB + (c + 1) * KCH);
#pragma unroll
            for (int i = 0; i < 4; i++) {
                uint32_t off = swz(lrow[i] * 128 + lkc * 16);
                CP_ASYNC16(bufA + off, srcA + (size_t)lrow[i] * KTOT * 2 + lkc * 16);
            }
            if (!diag) {
#pragma unroll
                for (int i = 0; i < 4; i++) {
                    uint32_t off = swz(lrow[i] * 128 + lkc * 16);
                    CP_ASYNC16(bufB + off, srcB + (size_t)lrow[i] * KTOT * 2 + lkc * 16);
                }
            }
            CP_COMMIT();
            CP_WAIT(1);
        } else {
            CP_WAIT(0);
        }
        __syncthreads();

        const uint32_t bA = tbase + (c & 1) * 32768u;
        const uint32_t bB = diag ? bA : bA + 16384u;

#pragma unroll
        for (int ks = 0; ks < 4; ks++) {
            uint32_t afr[4][4], bfr[4][2];
#pragma unroll
            for (int mt = 0; mt < 4; mt++) {
                int row = m0w + mt * 16 + (lid & 15);
                int ch = ks * 2 + (lid >> 4);
                ldmatrix_x4(afr[mt][0], afr[mt][1], afr[mt][2], afr[mt][3],
                            bA + swz(row * 128 + ch * 16));
            }
#pragma unroll
            for (int nt = 0; nt < 4; nt++) {
                int row = n0w + nt * 8 + (lid & 7);
                int ch = ks * 2 + ((lid >> 3) & 1);
                ldmatrix_x2(bfr[nt][0], bfr[nt][1], bB + swz(row * 128 + ch * 16));
            }
#pragma unroll
            for (int mt = 0; mt < 4; mt++)
#pragma unroll
                for (int nt = 0; nt < 4; nt++)
                    mma_bf16(acc[mt][nt], afr[mt], bfr[nt]);
        }
        __syncthreads();
    }

    // -------- epilogue from register fragments --------
    const int gID = lid >> 2;     // 0..7
    const int tig = lid & 3;      // 0..3

    float rs[4][2], cs[4][2];
#pragma unroll
    for (int x = 0; x < 4; x++) { rs[x][0] = rs[x][1] = 0.0f; cs[x][0] = cs[x][1] = 0.0f; }

#pragma unroll
    for (int mt = 0; mt < 4; mt++) {
        const int r0 = m0w + mt * 16 + gID;
        const int r1 = r0 + 8;
        const float mi0 = sMagI[r0], mi1 = sMagI[r1];
        const int li0 = sLabI[r0], li1 = sLabI[r1];
        const int gi_0 = gi0 + r0, gi_1 = gi0 + r1;
#pragma unroll
        for (int nt = 0; nt < 4; nt++) {
            const int c0 = n0w + nt * 8 + tig * 2;
            const int c1 = c0 + 1;
            const float mj0 = sMagJ[c0], mj1 = sMagJ[c1];
            const int lj0 = sLabJ[c0], lj1 = sLabJ[c1];
            const int gj_0 = gj0 + c0, gj_1 = gj0 + c1;

#define PROC(SIM, MI, LI, GI, MJ, LJ, GJ, RSUM, CSUM)                          \
            {                                                                  \
                float d2 = fmaxf((MI) + (MJ)-2.0f * (SIM), 0.0f);              \
                float dist = sqrtf(d2);                                        \
                if ((LI) != (LJ)) {                                            \
                    float e = (dist > 0.0f) ? __expf(MARGIN - dist) : 0.0f;    \
                    RSUM += e;                                                 \
                    CSUM += e;                                                 \
                } else if ((GI) < (GJ)) {                                      \
                    unsigned p = atomicAdd(&sNpos, 1u);                        \
                    unsigned key = ((unsigned)(GI) << 12) | (unsigned)(GJ);    \
                    if (p < CAP) { sPosKey[p] = key; sPosDist[p] = dist; }     \
                    else {                                                     \
                        unsigned q = atomicAdd(&g_npos, 1u);                   \
                        g_pos_key[q] = key;                                    \
                        g_pos_dist[q] = dist;                                  \
                    }                                                          \
                }                                                              \
            }
            PROC(acc[mt][nt][0], mi0, li0, gi_0, mj0, lj0, gj_0, rs[mt][0], cs[nt][0]);
            PROC(acc[mt][nt][1], mi0, li0, gi_0, mj1, lj1, gj_1, rs[mt][0], cs[nt][1]);
            PROC(acc[mt][nt][2], mi1, li1, gi_1, mj0, lj0, gj_0, rs[mt][1], cs[nt][0]);
            PROC(acc[mt][nt][3], mi1, li1, gi_1, mj1, lj1, gj_1, rs[mt][1], cs[nt][1]);
#undef PROC
        }
    }

    // row sums: reduce across lanes with same gID (xor low 2 bits)
#pragma unroll
    for (int mt = 0; mt < 4; mt++) {
        float v0 = rs[mt][0], v1 = rs[mt][1];
        v0 += __shfl_xor_sync(0xffffffffu, v0, 1);
        v0 += __shfl_xor_sync(0xffffffffu, v0, 2);
        v1 += __shfl_xor_sync(0xffffffffu, v1, 1);
        v1 += __shfl_xor_sync(0xffffffffu, v1, 2);
        if (tig == 0) {
            atomicAdd(&sRow[m0w + mt * 16 + gID], v0);
            atomicAdd(&sRow[m0w + mt * 16 + gID + 8], v1);
        }
    }
    // col sums: reduce across gID (xor bits 2..4); skip for diagonal tiles
    if (!diag) {
#pragma unroll
        for (int nt = 0; nt < 4; nt++) {
            float w0 = cs[nt][0], w1 = cs[nt][1];
            w0 += __shfl_xor_sync(0xffffffffu, w0, 4);
            w0 += __shfl_xor_sync(0xffffffffu, w0, 8);
            w0 += __shfl_xor_sync(0xffffffffu, w0, 16);
            w1 += __shfl_xor_sync(0xffffffffu, w1, 4);
            w1 += __shfl_xor_sync(0xffffffffu, w1, 8);
            w1 += __shfl_xor_sync(0xffffffffu, w1, 16);
            if (lid < 4) {
                atomicAdd(&sCol[n0w + nt * 8 + lid * 2], w0);
                atomicAdd(&sCol[n0w + nt * 8 + lid * 2 + 1], w1);
            }
        }
    }
    __syncthreads();

    if (tid < TILE) {
        atomicAdd(&g_rowneg[gi0 + tid], sRow[tid]);
        if (!diag) atomicAdd(&g_rowneg[gj0 + tid], sCol[tid]);
    }

    // flush buffered positive pairs with one reservation
    if (tid == 0) {
        unsigned np = sNpos < CAP ? sNpos : CAP;
        sBase = atomicAdd(&g_npos, np);
    }
    __syncthreads();
    const unsigned np = sNpos < CAP ? sNpos : CAP;
    for (unsigned k2 = tid; k2 < np; k2 += GTHREADS) {
        g_pos_key[sBase + k2] = sPosKey[k2];
        g_pos_dist[sBase + k2] = sPosDist[k2];
    }
}

// ---------------- positive-pair loss over the recorded list ----------------
__global__ void k_loss2() {
    const unsigned total = g_npos;
    double lsum = 0.0;
    for (unsigned t = blockIdx.x * blockDim.x + threadIdx.x; t < total;
         t += gridDim.x * blockDim.x) {
        unsigned key = g_pos_key[t];
        float dist = g_pos_dist[t];
        int i = key >> 12;
        int j = key & 4095;
        float J = logf(g_rowneg[i] + g_rowneg[j]) + dist;
        float l = fmaxf(J, 0.0f);
        lsum += (double)l * (double)l;
    }
    __shared__ double sl[256];
    int tid = threadIdx.x;
    sl[tid] = lsum;
    __syncthreads();
    for (int s = 128; s > 0; s >>= 1) {
        if (tid < s) sl[tid] += sl[tid + s];
        __syncthreads();
    }
    if (tid == 0 && sl[0] != 0.0) atomicAdd(&g_loss, sl[0]);
}

// ---------------- finalize ----------------
__global__ void k_final(float* __restrict__ out) {
    out[0] = (float)(g_loss / (double)(2ULL * (unsigned long long)g_npos));
}

extern "C" void kernel_launch(void* const* d_in, const int* in_sizes, int n_in,
                              void* d_out, int out_size) {
    const float* X = (const float*)d_in[0];
    const int* lab = (const int*)d_in[1];
    float* out = (float*)d_out;

    cudaFuncSetAttribute(k_gemm, cudaFuncAttributeMaxDynamicSharedMemorySize, 66560);

    k_init<<<(N + 255) / 256, 256>>>();
    k_prep<<<N, 128>>>(X);
    k_gemm<<<NPAIR_TILES, GTHREADS, 66560>>>(lab);
    k_loss2<<<256, 256>>>();
    k_final<<<1, 1>>>(out);
}